// round 4
// baseline (speedup 1.0000x reference)
#include <cuda_runtime.h>

// Problem constants
#define NB     4
#define CIN    512
#define COUT   256
#define DDIM   256
#define SP     16384            // H*W = 128*128
#define NSPLIT 16
#define SCHUNK (SP / NSPLIT)    // 1024

// Scratch (device globals; no dynamic allocation allowed)
__device__ float g_k[(size_t)NB * COUT * SP];                 // 64 MiB: relu(bn(conv1))
__device__ float g_epart[(size_t)NB * NSPLIT * DDIM * COUT];  // 16 MiB: energy partials
__device__ float g_att[(size_t)NB * DDIM * COUT];             // 1 MiB
__device__ float g_m[(size_t)NB * COUT * DDIM];               // 1 MiB: W2 @ att^T

// ---------------------------------------------------------------------------
// NN SGEMM: C[M,N] = A[M,K] @ B[K,N], row-major. Tile 128x128xBK8, micro 8x8.
// Epilogue: BNRELU ? (x*scale+shift, relu) : (x + bias)
// grid = (N/128, M/128, NB)
// ---------------------------------------------------------------------------
template <bool BNRELU>
__global__ void __launch_bounds__(256) gemm_nn_k(
    const float* __restrict__ Abase, const float* __restrict__ Bbase,
    float* __restrict__ Cbase, int Kdim,
    size_t sA, size_t sB, size_t sC,
    const float* __restrict__ p0, const float* __restrict__ p1,
    const float* __restrict__ p2, const float* __restrict__ p3)
{
    const int Ndim = SP;
    const float* A = Abase + (size_t)blockIdx.z * sA;
    const float* B = Bbase + (size_t)blockIdx.z * sB;
    float* C = Cbase + (size_t)blockIdx.z * sC;
    const int tM = blockIdx.y * 128;
    const int tN = blockIdx.x * 128;

    __shared__ float As[8][128];
    __shared__ float Bs[8][128];

    const int tid = threadIdx.x;
    const int ar = tid >> 1;            // 0..127
    const int ac = (tid & 1) * 4;       // 0 or 4
    const int br = tid >> 5;            // 0..7
    const int bc = (tid & 31) * 4;      // 0..124
    const int mf = (tid >> 4) * 8;      // 0..120
    const int nf = (tid & 15) * 8;      // 0..120

    float acc[8][8];
#pragma unroll
    for (int i = 0; i < 8; i++)
#pragma unroll
        for (int j = 0; j < 8; j++) acc[i][j] = 0.f;

    for (int k0 = 0; k0 < Kdim; k0 += 8) {
        float4 av = *(const float4*)(A + (size_t)(tM + ar) * Kdim + k0 + ac);
        float4 bv = *(const float4*)(B + (size_t)(k0 + br) * Ndim + tN + bc);
        __syncthreads();
        As[ac + 0][ar] = av.x; As[ac + 1][ar] = av.y;
        As[ac + 2][ar] = av.z; As[ac + 3][ar] = av.w;
        *(float4*)&Bs[br][bc] = bv;
        __syncthreads();
#pragma unroll
        for (int k = 0; k < 8; k++) {
            float a[8], b[8];
            *(float4*)(a)     = *(const float4*)&As[k][mf];
            *(float4*)(a + 4) = *(const float4*)&As[k][mf + 4];
            *(float4*)(b)     = *(const float4*)&Bs[k][nf];
            *(float4*)(b + 4) = *(const float4*)&Bs[k][nf + 4];
#pragma unroll
            for (int i = 0; i < 8; i++)
#pragma unroll
                for (int j = 0; j < 8; j++) acc[i][j] = fmaf(a[i], b[j], acc[i][j]);
        }
    }

#pragma unroll
    for (int i = 0; i < 8; i++) {
        const int row = tM + mf + i;
        float sc, sh;
        if (BNRELU) {
            sc = p0[row] * rsqrtf(p3[row] + 1e-5f);
            sh = p1[row] - p2[row] * sc;
        } else {
            sc = 1.f;
            sh = p0[row];
        }
        float o[8];
#pragma unroll
        for (int j = 0; j < 8; j++) {
            float v = acc[i][j] * sc + sh;
            if (BNRELU) v = fmaxf(v, 0.f);
            o[j] = v;
        }
        float* cp = C + (size_t)row * Ndim + tN + nf;
        *(float4*)(cp)     = make_float4(o[0], o[1], o[2], o[3]);
        *(float4*)(cp + 4) = make_float4(o[4], o[5], o[6], o[7]);
    }
}

// ---------------------------------------------------------------------------
// Energy partials (NT GEMM): Epart[d,c] = sum_{s in chunk} Q[d,s] * K[c,s]
// Tile 128x128 over (d,c), split S into NSPLIT chunks. grid = (2, 2, NB*NSPLIT)
// ---------------------------------------------------------------------------
__global__ void __launch_bounds__(256) energy_k(const float* __restrict__ Q)
{
    const int n  = blockIdx.z >> 4;
    const int sp = blockIdx.z & 15;
    const float* A = Q   + (size_t)n * DDIM * SP + (size_t)sp * SCHUNK;  // rows d
    const float* B = g_k + (size_t)n * COUT * SP + (size_t)sp * SCHUNK;  // rows c
    float* C = g_epart + (size_t)(n * NSPLIT + sp) * DDIM * COUT;

    const int tI = blockIdx.y * 128;  // d tile
    const int tJ = blockIdx.x * 128;  // c tile

    __shared__ float As[8][128];
    __shared__ float Bs[8][128];

    const int tid = threadIdx.x;
    const int r  = tid >> 1;
    const int cc = (tid & 1) * 4;
    const int mf = (tid >> 4) * 8;
    const int nf = (tid & 15) * 8;

    float acc[8][8];
#pragma unroll
    for (int i = 0; i < 8; i++)
#pragma unroll
        for (int j = 0; j < 8; j++) acc[i][j] = 0.f;

    for (int k0 = 0; k0 < SCHUNK; k0 += 8) {
        float4 av = *(const float4*)(A + (size_t)(tI + r) * SP + k0 + cc);
        float4 bv = *(const float4*)(B + (size_t)(tJ + r) * SP + k0 + cc);
        __syncthreads();
        As[cc + 0][r] = av.x; As[cc + 1][r] = av.y;
        As[cc + 2][r] = av.z; As[cc + 3][r] = av.w;
        Bs[cc + 0][r] = bv.x; Bs[cc + 1][r] = bv.y;
        Bs[cc + 2][r] = bv.z; Bs[cc + 3][r] = bv.w;
        __syncthreads();
#pragma unroll
        for (int k = 0; k < 8; k++) {
            float a[8], b[8];
            *(float4*)(a)     = *(const float4*)&As[k][mf];
            *(float4*)(a + 4) = *(const float4*)&As[k][mf + 4];
            *(float4*)(b)     = *(const float4*)&Bs[k][nf];
            *(float4*)(b + 4) = *(const float4*)&Bs[k][nf + 4];
#pragma unroll
            for (int i = 0; i < 8; i++)
#pragma unroll
                for (int j = 0; j < 8; j++) acc[i][j] = fmaf(a[i], b[j], acc[i][j]);
        }
    }

#pragma unroll
    for (int i = 0; i < 8; i++) {
        float* cp = C + (size_t)(tI + mf + i) * COUT + tJ + nf;
        *(float4*)(cp)     = make_float4(acc[i][0], acc[i][1], acc[i][2], acc[i][3]);
        *(float4*)(cp + 4) = make_float4(acc[i][4], acc[i][5], acc[i][6], acc[i][7]);
    }
}

// ---------------------------------------------------------------------------
// Fused split-reduce + softmax.
// softmax(max_c(e)-e) over c  ==  exp(min_c(e)-e) / sum.  One block per (n,d).
// ---------------------------------------------------------------------------
__global__ void __launch_bounds__(256) softmax_k()
{
    const int nd = blockIdx.x;          // n*DDIM + d
    const int n = nd / DDIM;
    const int d = nd % DDIM;
    const int c = threadIdx.x;

    float e = 0.f;
#pragma unroll
    for (int s = 0; s < NSPLIT; s++)
        e += g_epart[((size_t)(n * NSPLIT + s) * DDIM + d) * COUT + c];

    __shared__ float red[256];
    red[c] = e;
    __syncthreads();
    for (int off = 128; off > 0; off >>= 1) {
        if (c < off) red[c] = fminf(red[c], red[c + off]);
        __syncthreads();
    }
    const float emin = red[0];
    __syncthreads();

    const float ex = expf(emin - e);
    red[c] = ex;
    __syncthreads();
    for (int off = 128; off > 0; off >>= 1) {
        if (c < off) red[c] += red[c + off];
        __syncthreads();
    }
    g_att[(size_t)nd * COUT + c] = ex / red[0];
}

// ---------------------------------------------------------------------------
// M[o,d] = sum_c W2[o,c] * att[d,c]   (NT GEMM, 64x64 tile, micro 4x4)
// grid = (DDIM/64, COUT/64, NB)
// ---------------------------------------------------------------------------
__global__ void __launch_bounds__(256) mmul_k(const float* __restrict__ w2)
{
    const int n = blockIdx.z;
    const float* A = w2;                                   // [o,c] ld COUT
    const float* B = g_att + (size_t)n * DDIM * COUT;      // [d,c] ld COUT
    float* C = g_m + (size_t)n * COUT * DDIM;              // [o,d] ld DDIM

    const int tI = blockIdx.y * 64;   // o
    const int tJ = blockIdx.x * 64;   // d

    __shared__ float As[16][64];
    __shared__ float Bs[16][64];

    const int tid = threadIdx.x;
    const int r  = tid >> 2;            // 0..63
    const int cc = (tid & 3) * 4;       // 0..12
    const int ifr = (tid >> 4) * 4;     // 0..60
    const int jfr = (tid & 15) * 4;     // 0..60

    float acc[4][4];
#pragma unroll
    for (int i = 0; i < 4; i++)
#pragma unroll
        for (int j = 0; j < 4; j++) acc[i][j] = 0.f;

    for (int k0 = 0; k0 < COUT; k0 += 16) {
        float4 av = *(const float4*)(A + (size_t)(tI + r) * COUT + k0 + cc);
        float4 bv = *(const float4*)(B + (size_t)(tJ + r) * COUT + k0 + cc);
        __syncthreads();
        As[cc + 0][r] = av.x; As[cc + 1][r] = av.y;
        As[cc + 2][r] = av.z; As[cc + 3][r] = av.w;
        Bs[cc + 0][r] = bv.x; Bs[cc + 1][r] = bv.y;
        Bs[cc + 2][r] = bv.z; Bs[cc + 3][r] = bv.w;
        __syncthreads();
#pragma unroll
        for (int k = 0; k < 16; k++) {
            float a[4], b[4];
            *(float4*)(a) = *(const float4*)&As[k][ifr];
            *(float4*)(b) = *(const float4*)&Bs[k][jfr];
#pragma unroll
            for (int i = 0; i < 4; i++)
#pragma unroll
                for (int j = 0; j < 4; j++) acc[i][j] = fmaf(a[i], b[j], acc[i][j]);
        }
    }

#pragma unroll
    for (int i = 0; i < 4; i++) {
        float* cp = C + (size_t)(tI + ifr + i) * DDIM + tJ + jfr;
        *(float4*)(cp) = make_float4(acc[i][0], acc[i][1], acc[i][2], acc[i][3]);
    }
}

// ---------------------------------------------------------------------------
extern "C" void kernel_launch(void* const* d_in, const int* in_sizes, int n_in,
                              void* d_out, int out_size)
{
    const float* feat  = (const float*)d_in[0];  // [4,512,128,128]
    const float* q     = (const float*)d_in[1];  // [4,256,128,128]
    const float* w1    = (const float*)d_in[2];  // [256,512]
    const float* gamma = (const float*)d_in[3];
    const float* beta  = (const float*)d_in[4];
    const float* mean  = (const float*)d_in[5];
    const float* var   = (const float*)d_in[6];
    const float* w2    = (const float*)d_in[7];  // [256,256]
    const float* b2    = (const float*)d_in[8];
    float* out = (float*)d_out;

    void *kaddr = nullptr, *maddr = nullptr;
    cudaGetSymbolAddress(&kaddr, g_k);
    cudaGetSymbolAddress(&maddr, g_m);
    float* kbuf = (float*)kaddr;
    float* mbuf = (float*)maddr;

    const dim3 thr(256);

    // 1) K = relu(bn(W1 @ F))   [per batch: 256x16384, K=512]
    gemm_nn_k<true><<<dim3(SP / 128, COUT / 128, NB), thr>>>(
        w1, feat, kbuf, CIN,
        (size_t)0, (size_t)CIN * SP, (size_t)COUT * SP,
        gamma, beta, mean, var);

    // 2) energy partials: E[d,c] = Q . K^T, split-S
    energy_k<<<dim3(COUT / 128, DDIM / 128, NB * NSPLIT), thr>>>(q);

    // 3) reduce + softmax -> attention
    softmax_k<<<NB * DDIM, 256>>>();

    // 4) M = W2 @ att^T
    mmul_k<<<dim3(DDIM / 64, COUT / 64, NB), thr>>>(w2);

    // 5) out = M @ Q + b2
    gemm_nn_k<false><<<dim3(SP / 128, COUT / 128, NB), thr>>>(
        mbuf, q, out, DDIM,
        (size_t)COUT * DDIM, (size_t)DDIM * SP, (size_t)COUT * SP,
        b2, nullptr, nullptr, nullptr);
}

// round 5
// speedup vs baseline: 1.1053x; 1.1053x over previous
#include <cuda_runtime.h>

// Problem constants
#define NB     4
#define CIN    512
#define COUT   256
#define DDIM   256
#define SP     16384            // H*W = 128*128
#define NSPLIT 16
#define SCHUNK (SP / NSPLIT)    // 1024

// Scratch (device globals; no dynamic allocation allowed)
__device__ float g_k[(size_t)NB * COUT * SP];                 // 64 MiB
__device__ float g_epart[(size_t)NB * NSPLIT * DDIM * COUT];  // 16 MiB
__device__ float g_att[(size_t)NB * DDIM * COUT];             // 1 MiB
__device__ float g_m[(size_t)NB * COUT * DDIM];               // 1 MiB

// ---- packed f32x2 helpers (Blackwell FFMA2 — only reachable via PTX) ------
__device__ __forceinline__ unsigned long long ffma2(
    unsigned long long a, unsigned long long b, unsigned long long c)
{
    unsigned long long d;
    asm("fma.rn.f32x2 %0, %1, %2, %3;" : "=l"(d) : "l"(a), "l"(b), "l"(c));
    return d;
}
__device__ __forceinline__ unsigned long long dup2(float x)
{
    unsigned long long r;
    unsigned u = __float_as_uint(x);
    asm("mov.b64 %0, {%1, %1};" : "=l"(r) : "r"(u));
    return r;
}
__device__ __forceinline__ float2 unpk(unsigned long long v)
{
    unsigned lo, hi;
    asm("mov.b64 {%0, %1}, %2;" : "=r"(lo), "=r"(hi) : "l"(v));
    return make_float2(__uint_as_float(lo), __uint_as_float(hi));
}

// ---------------------------------------------------------------------------
// NN SGEMM: C[M,N] = A[M,K] @ B[K,N], row-major. Tile 128x128xBK16, micro 8x8
// via f32x2 (acc packed along N). Epilogue: BNRELU ? bn+relu : +bias.
// grid = (SP/128, M/128, NB), 256 threads.
// ---------------------------------------------------------------------------
template <bool BNRELU>
__global__ void __launch_bounds__(256, 2) gemm_nn_k(
    const float* __restrict__ Abase, const float* __restrict__ Bbase,
    float* __restrict__ Cbase, int Kdim,
    size_t sA, size_t sB, size_t sC,
    const float* __restrict__ p0, const float* __restrict__ p1,
    const float* __restrict__ p2, const float* __restrict__ p3)
{
    const int Ndim = SP;
    const float* A = Abase + (size_t)blockIdx.z * sA;
    const float* B = Bbase + (size_t)blockIdx.z * sB;
    float* C = Cbase + (size_t)blockIdx.z * sC;
    const int tM = blockIdx.y * 128;
    const int tN = blockIdx.x * 128;

    __shared__ __align__(16) float As[16][128];
    __shared__ __align__(16) float Bs[16][128];

    const int tid = threadIdx.x;
    const int ar = tid >> 1;            // 0..127  (M row within tile)
    const int ac = (tid & 1) * 4;       // 0 or 4  (k sub-col; +8 for 2nd vec)
    const int br = tid >> 5;            // 0..7    (k row; +8 for 2nd vec)
    const int bc = (tid & 31) * 4;      // 0..124
    const int mf = (tid >> 4) * 8;      // 0..120
    const int nf = (tid & 15) * 8;      // 0..120

    unsigned long long acc[8][4];
#pragma unroll
    for (int i = 0; i < 8; i++)
#pragma unroll
        for (int j = 0; j < 4; j++) acc[i][j] = 0ULL;

    for (int k0 = 0; k0 < Kdim; k0 += 16) {
        float4 av0 = *(const float4*)(A + (size_t)(tM + ar) * Kdim + k0 + ac);
        float4 av1 = *(const float4*)(A + (size_t)(tM + ar) * Kdim + k0 + ac + 8);
        float4 bv0 = *(const float4*)(B + (size_t)(k0 + br) * Ndim + tN + bc);
        float4 bv1 = *(const float4*)(B + (size_t)(k0 + br + 8) * Ndim + tN + bc);
        __syncthreads();
        As[ac + 0][ar] = av0.x; As[ac + 1][ar] = av0.y;
        As[ac + 2][ar] = av0.z; As[ac + 3][ar] = av0.w;
        As[ac + 8][ar] = av1.x; As[ac + 9][ar] = av1.y;
        As[ac +10][ar] = av1.z; As[ac +11][ar] = av1.w;
        *(float4*)&Bs[br][bc]     = bv0;
        *(float4*)&Bs[br + 8][bc] = bv1;
        __syncthreads();
#pragma unroll
        for (int k = 0; k < 16; k++) {
            float4 af0 = *(const float4*)&As[k][mf];
            float4 af1 = *(const float4*)&As[k][mf + 4];
            ulonglong2 bq0 = *(const ulonglong2*)&Bs[k][nf];
            ulonglong2 bq1 = *(const ulonglong2*)&Bs[k][nf + 4];
            unsigned long long ad[8] = {
                dup2(af0.x), dup2(af0.y), dup2(af0.z), dup2(af0.w),
                dup2(af1.x), dup2(af1.y), dup2(af1.z), dup2(af1.w)};
            unsigned long long bp[4] = {bq0.x, bq0.y, bq1.x, bq1.y};
#pragma unroll
            for (int i = 0; i < 8; i++)
#pragma unroll
                for (int j = 0; j < 4; j++)
                    acc[i][j] = ffma2(ad[i], bp[j], acc[i][j]);
        }
    }

#pragma unroll
    for (int i = 0; i < 8; i++) {
        const int row = tM + mf + i;
        float sc, sh;
        if (BNRELU) {
            sc = p0[row] * rsqrtf(p3[row] + 1e-5f);
            sh = p1[row] - p2[row] * sc;
        } else {
            sc = 1.f;
            sh = p0[row];
        }
        float o[8];
#pragma unroll
        for (int j = 0; j < 4; j++) {
            float2 f = unpk(acc[i][j]);
            float v0 = f.x * sc + sh;
            float v1 = f.y * sc + sh;
            if (BNRELU) { v0 = fmaxf(v0, 0.f); v1 = fmaxf(v1, 0.f); }
            o[2 * j] = v0; o[2 * j + 1] = v1;
        }
        float* cp = C + (size_t)row * Ndim + tN + nf;
        *(float4*)(cp)     = make_float4(o[0], o[1], o[2], o[3]);
        *(float4*)(cp + 4) = make_float4(o[4], o[5], o[6], o[7]);
    }
}

// ---------------------------------------------------------------------------
// Energy partials (NT GEMM): Epart[d,c] = sum_{s in chunk} Q[d,s] * K[c,s]
// Tile 128x128xBK16 over (d,c), f32x2 micro 8x8. grid = (2, 2, NB*NSPLIT)
// ---------------------------------------------------------------------------
__global__ void __launch_bounds__(256, 2) energy_k(const float* __restrict__ Q)
{
    const int n  = blockIdx.z >> 4;
    const int sp = blockIdx.z & 15;
    const float* A = Q   + (size_t)n * DDIM * SP + (size_t)sp * SCHUNK;  // rows d
    const float* B = g_k + (size_t)n * COUT * SP + (size_t)sp * SCHUNK;  // rows c
    float* C = g_epart + (size_t)(n * NSPLIT + sp) * DDIM * COUT;

    const int tI = blockIdx.y * 128;  // d tile
    const int tJ = blockIdx.x * 128;  // c tile

    __shared__ __align__(16) float As[16][128];
    __shared__ __align__(16) float Bs[16][128];

    const int tid = threadIdx.x;
    const int r  = tid >> 1;            // 0..127
    const int cc = (tid & 1) * 4;       // 0 or 4 (+8 for second vec)
    const int mf = (tid >> 4) * 8;
    const int nf = (tid & 15) * 8;

    unsigned long long acc[8][4];
#pragma unroll
    for (int i = 0; i < 8; i++)
#pragma unroll
        for (int j = 0; j < 4; j++) acc[i][j] = 0ULL;

    for (int k0 = 0; k0 < SCHUNK; k0 += 16) {
        float4 av0 = *(const float4*)(A + (size_t)(tI + r) * SP + k0 + cc);
        float4 av1 = *(const float4*)(A + (size_t)(tI + r) * SP + k0 + cc + 8);
        float4 bv0 = *(const float4*)(B + (size_t)(tJ + r) * SP + k0 + cc);
        float4 bv1 = *(const float4*)(B + (size_t)(tJ + r) * SP + k0 + cc + 8);
        __syncthreads();
        As[cc + 0][r] = av0.x; As[cc + 1][r] = av0.y;
        As[cc + 2][r] = av0.z; As[cc + 3][r] = av0.w;
        As[cc + 8][r] = av1.x; As[cc + 9][r] = av1.y;
        As[cc +10][r] = av1.z; As[cc +11][r] = av1.w;
        Bs[cc + 0][r] = bv0.x; Bs[cc + 1][r] = bv0.y;
        Bs[cc + 2][r] = bv0.z; Bs[cc + 3][r] = bv0.w;
        Bs[cc + 8][r] = bv1.x; Bs[cc + 9][r] = bv1.y;
        Bs[cc +10][r] = bv1.z; Bs[cc +11][r] = bv1.w;
        __syncthreads();
#pragma unroll
        for (int k = 0; k < 16; k++) {
            float4 af0 = *(const float4*)&As[k][mf];
            float4 af1 = *(const float4*)&As[k][mf + 4];
            ulonglong2 bq0 = *(const ulonglong2*)&Bs[k][nf];
            ulonglong2 bq1 = *(const ulonglong2*)&Bs[k][nf + 4];
            unsigned long long ad[8] = {
                dup2(af0.x), dup2(af0.y), dup2(af0.z), dup2(af0.w),
                dup2(af1.x), dup2(af1.y), dup2(af1.z), dup2(af1.w)};
            unsigned long long bp[4] = {bq0.x, bq0.y, bq1.x, bq1.y};
#pragma unroll
            for (int i = 0; i < 8; i++)
#pragma unroll
                for (int j = 0; j < 4; j++)
                    acc[i][j] = ffma2(ad[i], bp[j], acc[i][j]);
        }
    }

#pragma unroll
    for (int i = 0; i < 8; i++) {
        float* cp = C + (size_t)(tI + mf + i) * COUT + tJ + nf;
        ulonglong2 s0; s0.x = acc[i][0]; s0.y = acc[i][1];
        ulonglong2 s1; s1.x = acc[i][2]; s1.y = acc[i][3];
        *(ulonglong2*)(cp)     = s0;
        *(ulonglong2*)(cp + 4) = s1;
    }
}

// ---------------------------------------------------------------------------
// Fused split-reduce + softmax.
// softmax(max_c(e)-e) over c  ==  exp(min_c(e)-e) / sum.  One block per (n,d).
// ---------------------------------------------------------------------------
__global__ void __launch_bounds__(256) softmax_k()
{
    const int nd = blockIdx.x;          // n*DDIM + d
    const int n = nd / DDIM;
    const int d = nd % DDIM;
    const int c = threadIdx.x;

    float e = 0.f;
#pragma unroll
    for (int s = 0; s < NSPLIT; s++)
        e += g_epart[((size_t)(n * NSPLIT + s) * DDIM + d) * COUT + c];

    __shared__ float red[256];
    red[c] = e;
    __syncthreads();
    for (int off = 128; off > 0; off >>= 1) {
        if (c < off) red[c] = fminf(red[c], red[c + off]);
        __syncthreads();
    }
    const float emin = red[0];
    __syncthreads();

    const float ex = expf(emin - e);
    red[c] = ex;
    __syncthreads();
    for (int off = 128; off > 0; off >>= 1) {
        if (c < off) red[c] += red[c + off];
        __syncthreads();
    }
    g_att[(size_t)nd * COUT + c] = ex / red[0];
}

// ---------------------------------------------------------------------------
// M[o,d] = sum_c W2[o,c] * att[d,c]   (NT GEMM, 32x32 tile, micro 2x2)
// grid = (DDIM/32, COUT/32, NB) = 256 blocks for occupancy.
// ---------------------------------------------------------------------------
__global__ void __launch_bounds__(256) mmul_k(const float* __restrict__ w2)
{
    const int n = blockIdx.z;
    const float* A = w2;                                   // [o,c] ld COUT
    const float* B = g_att + (size_t)n * DDIM * COUT;      // [d,c] ld COUT
    float* C = g_m + (size_t)n * COUT * DDIM;              // [o,d] ld DDIM

    const int tI = blockIdx.y * 32;   // o
    const int tJ = blockIdx.x * 32;   // d

    __shared__ float As[32][33];
    __shared__ float Bs[32][33];

    const int tid = threadIdx.x;
    const int r  = tid >> 3;            // 0..31
    const int c4 = (tid & 7) * 4;       // 0..28
    const int io = (tid >> 4) * 2;      // 0..30
    const int jo = (tid & 15) * 2;      // 0..30

    float acc[2][2] = {{0.f, 0.f}, {0.f, 0.f}};

    for (int k0 = 0; k0 < COUT; k0 += 32) {
        float4 av = *(const float4*)(A + (size_t)(tI + r) * COUT + k0 + c4);
        float4 bv = *(const float4*)(B + (size_t)(tJ + r) * COUT + k0 + c4);
        __syncthreads();
        As[c4 + 0][r] = av.x; As[c4 + 1][r] = av.y;
        As[c4 + 2][r] = av.z; As[c4 + 3][r] = av.w;
        Bs[c4 + 0][r] = bv.x; Bs[c4 + 1][r] = bv.y;
        Bs[c4 + 2][r] = bv.z; Bs[c4 + 3][r] = bv.w;
        __syncthreads();
#pragma unroll
        for (int k = 0; k < 32; k++) {
            float a0 = As[k][io], a1 = As[k][io + 1];
            float b0 = Bs[k][jo], b1 = Bs[k][jo + 1];
            acc[0][0] = fmaf(a0, b0, acc[0][0]);
            acc[0][1] = fmaf(a0, b1, acc[0][1]);
            acc[1][0] = fmaf(a1, b0, acc[1][0]);
            acc[1][1] = fmaf(a1, b1, acc[1][1]);
        }
    }

#pragma unroll
    for (int i = 0; i < 2; i++)
#pragma unroll
        for (int j = 0; j < 2; j++)
            C[(size_t)(tI + io + i) * DDIM + tJ + jo + j] = acc[i][j];
}

// ---------------------------------------------------------------------------
extern "C" void kernel_launch(void* const* d_in, const int* in_sizes, int n_in,
                              void* d_out, int out_size)
{
    const float* feat  = (const float*)d_in[0];  // [4,512,128,128]
    const float* q     = (const float*)d_in[1];  // [4,256,128,128]
    const float* w1    = (const float*)d_in[2];  // [256,512]
    const float* gamma = (const float*)d_in[3];
    const float* beta  = (const float*)d_in[4];
    const float* mean  = (const float*)d_in[5];
    const float* var   = (const float*)d_in[6];
    const float* w2    = (const float*)d_in[7];  // [256,256]
    const float* b2    = (const float*)d_in[8];
    float* out = (float*)d_out;

    void *kaddr = nullptr, *maddr = nullptr;
    cudaGetSymbolAddress(&kaddr, g_k);
    cudaGetSymbolAddress(&maddr, g_m);
    float* kbuf = (float*)kaddr;
    float* mbuf = (float*)maddr;

    const dim3 thr(256);

    // 1) K = relu(bn(W1 @ F))   [per batch: 256x16384, K=512]
    gemm_nn_k<true><<<dim3(SP / 128, COUT / 128, NB), thr>>>(
        w1, feat, kbuf, CIN,
        (size_t)0, (size_t)CIN * SP, (size_t)COUT * SP,
        gamma, beta, mean, var);

    // 2) energy partials: E[d,c] = Q . K^T, split-S
    energy_k<<<dim3(COUT / 128, DDIM / 128, NB * NSPLIT), thr>>>(q);

    // 3) reduce + softmax -> attention
    softmax_k<<<NB * DDIM, 256>>>();

    // 4) M = W2 @ att^T
    mmul_k<<<dim3(DDIM / 32, COUT / 32, NB), thr>>>(w2);

    // 5) out = M @ Q + b2
    gemm_nn_k<false><<<dim3(SP / 128, COUT / 128, NB), thr>>>(
        mbuf, q, out, DDIM,
        (size_t)COUT * DDIM, (size_t)DDIM * SP, (size_t)COUT * SP,
        b2, nullptr, nullptr, nullptr);
}

// round 10
// speedup vs baseline: 1.1577x; 1.0474x over previous
#include <cuda_runtime.h>
#include <cuda_bf16.h>
#include <cstdint>

// Problem constants
#define NB     4
#define CIN    512
#define COUT   256
#define DDIM   256
#define SP     16384            // H*W
#define NSPLIT 16
#define SCHUNK (SP / NSPLIT)    // 1024

#define TILE   128
#define KC     64               // K per chunk (bf16: 128B rows = SW128 atom)
#define TILE_BYTES (TILE * KC * 2)      // 16384
#define SMEM_DYN   (6 * TILE_BYTES)     // 98304

// Scratch
__device__ float g_k[(size_t)NB * COUT * SP];                 // 64 MiB
__device__ float g_epart[(size_t)NB * NSPLIT * DDIM * COUT];  // 16 MiB
__device__ float g_att[(size_t)NB * DDIM * COUT];             // 1 MiB
__device__ float g_m[(size_t)NB * COUT * DDIM];               // 1 MiB

// ---------------- helpers ---------------------------------------------------
__device__ __forceinline__ uint32_t smem_u32(const void* p) {
    uint32_t a;
    asm("{ .reg .u64 t; cvta.to.shared.u64 t, %1; cvt.u32.u64 %0, t; }"
        : "=r"(a) : "l"(p));
    return a;
}

__device__ __forceinline__ uint32_t swz(uint32_t b) { return b ^ ((b >> 3) & 0x70); }

// ldmatrix x4 (non-transposed), b16
__device__ __forceinline__ void ldsm4(uint32_t* r, uint32_t addr)
{
    asm volatile("ldmatrix.sync.aligned.m8n8.x4.shared.b16 {%0,%1,%2,%3}, [%4];"
                 : "=r"(r[0]), "=r"(r[1]), "=r"(r[2]), "=r"(r[3]) : "r"(addr));
}

// D += A*B  (m16n8k16, bf16 in, fp32 acc)
__device__ __forceinline__ void mma16816(float* c, const uint32_t* a, const uint32_t* b)
{
    asm volatile(
        "mma.sync.aligned.m16n8k16.row.col.f32.bf16.bf16.f32 "
        "{%0,%1,%2,%3}, {%4,%5,%6,%7}, {%8,%9}, {%0,%1,%2,%3};"
        : "+f"(c[0]), "+f"(c[1]), "+f"(c[2]), "+f"(c[3])
        : "r"(a[0]), "r"(a[1]), "r"(a[2]), "r"(a[3]), "r"(b[0]), "r"(b[1]));
}

// Split fp32 -> 3 bf16 components (x ~= h1 + h2 + h3)
__device__ __forceinline__ void split3(float x, unsigned short& a,
                                       unsigned short& b, unsigned short& c)
{
    __nv_bfloat16 h1 = __float2bfloat16_rn(x);
    float r = x - __bfloat162float(h1);
    __nv_bfloat16 h2 = __float2bfloat16_rn(r);
    float r2 = r - __bfloat162float(h2);
    __nv_bfloat16 h3 = __float2bfloat16_rn(r2);
    a = __bfloat16_as_ushort(h1);
    b = __bfloat16_as_ushort(h2);
    c = __bfloat16_as_ushort(h3);
}

// Clean fill: tile[r][k] = g[r][k] (K-major rows), SW128-swizzled, 3 split tiles.
__device__ __forceinline__ void fill_clean(char* tiles, const float* g, int ld, int tid)
{
    const int c16 = tid & 15;            // float4 index within 64-col row
    const int rb  = tid >> 4;            // row base 0..15
#pragma unroll
    for (int it = 0; it < 8; it++) {
        const int r = rb + it * 16;
        float4 v = *(const float4*)(g + (size_t)r * ld + c16 * 4);
        unsigned long long u1 = 0, u2 = 0, u3 = 0;
        const float xs[4] = {v.x, v.y, v.z, v.w};
#pragma unroll
        for (int j = 0; j < 4; j++) {
            unsigned short a, b, c;
            split3(xs[j], a, b, c);
            u1 |= (unsigned long long)a << (16 * j);
            u2 |= (unsigned long long)b << (16 * j);
            u3 |= (unsigned long long)c << (16 * j);
        }
        const uint32_t sw = swz((uint32_t)r * 128u + (uint32_t)c16 * 8u);
        *(unsigned long long*)(tiles + sw)                  = u1;
        *(unsigned long long*)(tiles + TILE_BYTES + sw)     = u2;
        *(unsigned long long*)(tiles + 2 * TILE_BYTES + sw) = u3;
    }
}

// Transposed fill: tile[n][k] = g[k][n]. g points at (k-row 0 of chunk, col n0).
__device__ __forceinline__ void fill_trans(char* tiles, const float* g, int ld, int tid)
{
    const int bk = (tid >> 2) & 15;                    // k-block 0..15
    const int bn0 = (tid & 3) | ((tid >> 6) << 2);     // n-block 0..7
#pragma unroll
    for (int it = 0; it < 2; it++) {
        const int bn = bn0 + it * 16;
        float4 rowv[4];
#pragma unroll
        for (int j = 0; j < 4; j++)
            rowv[j] = *(const float4*)(g + (size_t)(bk * 4 + j) * ld + bn * 4);
        const float* rp = (const float*)rowv;
#pragma unroll
        for (int i = 0; i < 4; i++) {
            unsigned long long u1 = 0, u2 = 0, u3 = 0;
#pragma unroll
            for (int j = 0; j < 4; j++) {
                unsigned short a, b, c;
                split3(rp[j * 4 + i], a, b, c);
                u1 |= (unsigned long long)a << (16 * j);
                u2 |= (unsigned long long)b << (16 * j);
                u3 |= (unsigned long long)c << (16 * j);
            }
            const uint32_t sw = swz((uint32_t)(bn * 4 + i) * 128u + (uint32_t)bk * 8u);
            *(unsigned long long*)(tiles + sw)                  = u1;
            *(unsigned long long*)(tiles + TILE_BYTES + sw)     = u2;
            *(unsigned long long*)(tiles + 2 * TILE_BYTES + sw) = u3;
        }
    }
}

// ---------------------------------------------------------------------------
// Tensor-core GEMM via warp-level mma.sync (HMMA).
//   MODE 0: conv1  (A=w1 clean, B=feat trans, epi BN+ReLU)
//   MODE 1: energy (A=Q clean, B=g_k clean, epi raw, split-S by blockIdx.z)
//   MODE 2: conv2  (A=g_m clean, B=q trans, epi +bias)
// 128x128 tile, 8 warps in 2(m) x 4(n) grid, warp tile 64x32.
// ---------------------------------------------------------------------------
template <int MODE>
__global__ void __launch_bounds__(256) tc_gemm(
    const float* __restrict__ Abase, int lda, size_t sAz,
    const float* __restrict__ Bbase, int ldb, size_t sBz,
    float* __restrict__ Cbase, int ldc, size_t sCz,
    int Kdim,
    const float* __restrict__ p0, const float* __restrict__ p1,
    const float* __restrict__ p2, const float* __restrict__ p3)
{
    extern __shared__ char sm[];
    const uint32_t smb = smem_u32(sm);
    const int tid = threadIdx.x;
    const int wid = tid >> 5;
    const int lane = tid & 31;
    const int warp_m = wid >> 2;     // 0..1
    const int warp_n = wid & 3;      // 0..3

    const float* A;
    const float* B;
    float* C;
    if (MODE == 1) {
        const int n = blockIdx.z >> 4, sp = blockIdx.z & 15;
        A = Abase + (size_t)n * DDIM * SP + (size_t)sp * SCHUNK;
        B = Bbase + (size_t)n * COUT * SP + (size_t)sp * SCHUNK;
        C = Cbase + (size_t)blockIdx.z * DDIM * COUT;
    } else {
        A = Abase + (size_t)blockIdx.z * sAz;
        B = Bbase + (size_t)blockIdx.z * sBz;
        C = Cbase + (size_t)blockIdx.z * sCz;
    }
    const int tM = blockIdx.y * TILE;
    const int tN = blockIdx.x * TILE;

    char* tilesA = sm;
    char* tilesB = sm + 3 * TILE_BYTES;

    float acc[4][4][4];
#pragma unroll
    for (int i = 0; i < 4; i++)
#pragma unroll
        for (int j = 0; j < 4; j++)
#pragma unroll
            for (int v = 0; v < 4; v++) acc[i][j][v] = 0.f;

    // ldmatrix per-thread address components.
    // A x4 mats: [m0-7,k0-7],[m8-15,k0-7],[m0-7,k8-15],[m8-15,k8-15]
    const int a_row_c = warp_m * 64 + ((tid >> 3) & 1) * 8 + (tid & 7);
    const int a_k_c   = ((tid >> 4) & 1) * 16;   // bytes
    // B x4 mats: [n(2jj)*8,k0-7],[same n,k8-15],[n(2jj+1)*8,k0-7],[...,k8-15]
    const int b_row_c = warp_n * 32 + ((tid >> 4) & 1) * 8 + (tid & 7);
    const int b_k_c   = ((tid >> 3) & 1) * 16;   // bytes

    const int pa[6] = {0, 0, 1, 1, 0, 2};
    const int pb[6] = {0, 1, 0, 1, 2, 0};

    const int nch = Kdim / KC;
    for (int ch = 0; ch < nch; ch++) {
        fill_clean(tilesA, A + (size_t)tM * lda + ch * KC, lda, tid);
        if (MODE == 1)
            fill_clean(tilesB, B + (size_t)tN * ldb + ch * KC, ldb, tid);
        else
            fill_trans(tilesB, B + (size_t)(ch * KC) * ldb + tN, ldb, tid);
        __syncthreads();

#pragma unroll
        for (int p = 0; p < 6; p++) {
            const uint32_t baseA = smb + (uint32_t)pa[p] * TILE_BYTES;
            const uint32_t baseB = smb + (uint32_t)(3 + pb[p]) * TILE_BYTES;
#pragma unroll
            for (int ks = 0; ks < 4; ks++) {
                uint32_t af[4][4];
#pragma unroll
                for (int mf = 0; mf < 4; mf++)
                    ldsm4(af[mf], baseA + swz((uint32_t)(a_row_c + mf * 16) * 128u
                                              + (uint32_t)(a_k_c + ks * 32)));
                uint32_t bf[2][4];
#pragma unroll
                for (int jj = 0; jj < 2; jj++)
                    ldsm4(bf[jj], baseB + swz((uint32_t)(b_row_c + jj * 16) * 128u
                                              + (uint32_t)(b_k_c + ks * 32)));
#pragma unroll
                for (int mf = 0; mf < 4; mf++)
#pragma unroll
                    for (int nf = 0; nf < 4; nf++)
                        mma16816(acc[mf][nf], af[mf], &bf[nf >> 1][(nf & 1) * 2]);
            }
        }
        __syncthreads();
    }

    // Epilogue. C frag m16n8: c0,c1 -> (row lane/4, col 2*(lane%4)+{0,1});
    // c2,c3 -> row+8.
#pragma unroll
    for (int mf = 0; mf < 4; mf++) {
        const int r0 = tM + warp_m * 64 + mf * 16 + (lane >> 2);
        const int r1 = r0 + 8;
        float sc0 = 1.f, sh0 = 0.f, sc1 = 1.f, sh1 = 0.f;
        if (MODE == 0) {
            sc0 = p0[r0] * rsqrtf(p3[r0] + 1e-5f);
            sh0 = p1[r0] - p2[r0] * sc0;
            sc1 = p0[r1] * rsqrtf(p3[r1] + 1e-5f);
            sh1 = p1[r1] - p2[r1] * sc1;
        } else if (MODE == 2) {
            sh0 = p0[r0];
            sh1 = p0[r1];
        }
#pragma unroll
        for (int nf = 0; nf < 4; nf++) {
            const int col = tN + warp_n * 32 + nf * 8 + (lane & 3) * 2;
            float v0 = acc[mf][nf][0], v1 = acc[mf][nf][1];
            float v2 = acc[mf][nf][2], v3 = acc[mf][nf][3];
            if (MODE == 0) {
                v0 = fmaxf(v0 * sc0 + sh0, 0.f);
                v1 = fmaxf(v1 * sc0 + sh0, 0.f);
                v2 = fmaxf(v2 * sc1 + sh1, 0.f);
                v3 = fmaxf(v3 * sc1 + sh1, 0.f);
            } else if (MODE == 2) {
                v0 += sh0; v1 += sh0; v2 += sh1; v3 += sh1;
            }
            *(float2*)(C + (size_t)r0 * ldc + col) = make_float2(v0, v1);
            *(float2*)(C + (size_t)r1 * ldc + col) = make_float2(v2, v3);
        }
    }
}

// ---------------------------------------------------------------------------
// Fused split-reduce + softmax: softmax(max-e) == exp(min-e)/sum.
// ---------------------------------------------------------------------------
__global__ void __launch_bounds__(256) softmax_k()
{
    const int nd = blockIdx.x;
    const int n = nd / DDIM;
    const int d = nd % DDIM;
    const int c = threadIdx.x;

    float e = 0.f;
#pragma unroll
    for (int s = 0; s < NSPLIT; s++)
        e += g_epart[((size_t)(n * NSPLIT + s) * DDIM + d) * COUT + c];

    __shared__ float red[256];
    red[c] = e;
    __syncthreads();
    for (int off = 128; off > 0; off >>= 1) {
        if (c < off) red[c] = fminf(red[c], red[c + off]);
        __syncthreads();
    }
    const float emin = red[0];
    __syncthreads();

    const float ex = expf(emin - e);
    red[c] = ex;
    __syncthreads();
    for (int off = 128; off > 0; off >>= 1) {
        if (c < off) red[c] += red[c + off];
        __syncthreads();
    }
    g_att[(size_t)nd * COUT + c] = ex / red[0];
}

// ---------------------------------------------------------------------------
// M[o,d] = sum_c W2[o,c] * att[d,c]
// ---------------------------------------------------------------------------
__global__ void __launch_bounds__(256) mmul_k(const float* __restrict__ w2)
{
    const int n = blockIdx.z;
    const float* A = w2;
    const float* B = g_att + (size_t)n * DDIM * COUT;
    float* C = g_m + (size_t)n * COUT * DDIM;

    const int tI = blockIdx.y * 32;
    const int tJ = blockIdx.x * 32;

    __shared__ float As[32][33];
    __shared__ float Bs[32][33];

    const int tid = threadIdx.x;
    const int r  = tid >> 3;
    const int c4 = (tid & 7) * 4;
    const int io = (tid >> 4) * 2;
    const int jo = (tid & 15) * 2;

    float acc[2][2] = {{0.f, 0.f}, {0.f, 0.f}};

    for (int k0 = 0; k0 < COUT; k0 += 32) {
        float4 av = *(const float4*)(A + (size_t)(tI + r) * COUT + k0 + c4);
        float4 bv = *(const float4*)(B + (size_t)(tJ + r) * COUT + k0 + c4);
        __syncthreads();
        As[c4 + 0][r] = av.x; As[c4 + 1][r] = av.y;
        As[c4 + 2][r] = av.z; As[c4 + 3][r] = av.w;
        Bs[c4 + 0][r] = bv.x; Bs[c4 + 1][r] = bv.y;
        Bs[c4 + 2][r] = bv.z; Bs[c4 + 3][r] = bv.w;
        __syncthreads();
#pragma unroll
        for (int k = 0; k < 32; k++) {
            float a0 = As[k][io], a1 = As[k][io + 1];
            float b0 = Bs[k][jo], b1 = Bs[k][jo + 1];
            acc[0][0] = fmaf(a0, b0, acc[0][0]);
            acc[0][1] = fmaf(a0, b1, acc[0][1]);
            acc[1][0] = fmaf(a1, b0, acc[1][0]);
            acc[1][1] = fmaf(a1, b1, acc[1][1]);
        }
    }
#pragma unroll
    for (int i = 0; i < 2; i++)
#pragma unroll
        for (int j = 0; j < 2; j++)
            C[(size_t)(tI + io + i) * DDIM + tJ + jo + j] = acc[i][j];
}

// ---------------------------------------------------------------------------
extern "C" void kernel_launch(void* const* d_in, const int* in_sizes, int n_in,
                              void* d_out, int out_size)
{
    const float* feat  = (const float*)d_in[0];
    const float* q     = (const float*)d_in[1];
    const float* w1    = (const float*)d_in[2];
    const float* gamma = (const float*)d_in[3];
    const float* beta  = (const float*)d_in[4];
    const float* mean  = (const float*)d_in[5];
    const float* var   = (const float*)d_in[6];
    const float* w2    = (const float*)d_in[7];
    const float* b2    = (const float*)d_in[8];
    float* out = (float*)d_out;

    void *kaddr = nullptr, *maddr = nullptr, *eaddr = nullptr;
    cudaGetSymbolAddress(&kaddr, g_k);
    cudaGetSymbolAddress(&maddr, g_m);
    cudaGetSymbolAddress(&eaddr, g_epart);
    float* kbuf = (float*)kaddr;
    float* mbuf = (float*)maddr;
    float* ebuf = (float*)eaddr;

    cudaFuncSetAttribute(tc_gemm<0>, cudaFuncAttributeMaxDynamicSharedMemorySize, SMEM_DYN);
    cudaFuncSetAttribute(tc_gemm<1>, cudaFuncAttributeMaxDynamicSharedMemorySize, SMEM_DYN);
    cudaFuncSetAttribute(tc_gemm<2>, cudaFuncAttributeMaxDynamicSharedMemorySize, SMEM_DYN);

    // 1) K = relu(bn(W1 @ F)): M=COUT, N=SP, K=CIN
    tc_gemm<0><<<dim3(SP / TILE, COUT / TILE, NB), 256, SMEM_DYN>>>(
        w1, CIN, (size_t)0,
        feat, SP, (size_t)CIN * SP,
        kbuf, SP, (size_t)COUT * SP,
        CIN, gamma, beta, mean, var);

    // 2) energy partials: E[d,c] = Q . K^T, split-S
    tc_gemm<1><<<dim3(COUT / TILE, DDIM / TILE, NB * NSPLIT), 256, SMEM_DYN>>>(
        q, SP, (size_t)0,
        kbuf, SP, (size_t)0,
        ebuf, COUT, (size_t)0,
        SCHUNK, nullptr, nullptr, nullptr, nullptr);

    // 3) reduce + softmax -> attention
    softmax_k<<<NB * DDIM, 256>>>();

    // 4) M = W2 @ att^T
    mmul_k<<<dim3(DDIM / 32, COUT / 32, NB), 256>>>(w2);

    // 5) out = M @ Q + b2
    tc_gemm<2><<<dim3(SP / TILE, COUT / TILE, NB), 256, SMEM_DYN>>>(
        mbuf, DDIM, (size_t)COUT * DDIM,
        q, SP, (size_t)DDIM * SP,
        out, SP, (size_t)COUT * SP,
        DDIM, b2, nullptr, nullptr, nullptr);
}